// round 2
// baseline (speedup 1.0000x reference)
#include <cuda_runtime.h>
#include <math.h>

#define NUM_SPH 7
#define NUM_RAD 6
#define NBASIS  (NUM_SPH * NUM_RAD)   // 42
#define MAX_E   524288

// --------------------------------------------------------------------------
// Device-global scratch (static allocation only — no cudaMalloc allowed)
// --------------------------------------------------------------------------
__device__ float g_zeros[NUM_SPH][NUM_RAD];
__device__ float g_norms[NUM_SPH][NUM_RAD];
__device__ float g_rbf[(size_t)MAX_E * NBASIS];   // 88 MB, fits L2

// --------------------------------------------------------------------------
// fp64 spherical Bessel j_n via upward recurrence (matches reference _jn_np)
// --------------------------------------------------------------------------
__device__ double jn_d(int order, double r) {
    double s = sin(r), c = cos(r);
    double j0 = s / r;
    if (order == 0) return j0;
    double j1 = s / (r * r) - c / r;
    double jm = j0, jc = j1;
    for (int i = 1; i < order; ++i) {
        double jnext = (2.0 * i + 1.0) / r * jc - jm;
        jm = jc; jc = jnext;
    }
    return jc;
}

// --------------------------------------------------------------------------
// Setup: replicate _jn_zeros bisection (100 iters) + norms in fp64, cast fp32.
// Runs every call (no static init allowed); ~1 us, one block of 64 threads.
// (R1 bug: was 32 threads but final write loop needs tid < 42.)
// --------------------------------------------------------------------------
__global__ void setup_kernel() {
    __shared__ double points[16];
    __shared__ double racines[16];
    __shared__ double zeros_d[NUM_SPH][NUM_RAD];
    const double PI = 3.14159265358979323846;
    int tid = threadIdx.x;

    if (tid < NUM_RAD) zeros_d[0][tid] = (tid + 1) * PI;
    if (tid < NUM_RAD + NUM_SPH - 1) points[tid] = (tid + 1) * PI;  // 12 pts
    __syncthreads();

    for (int i = 1; i < NUM_SPH; ++i) {
        int cnt = NUM_RAD + NUM_SPH - 1 - i;   // 12 - i
        double root = 0.0;
        if (tid < cnt) {
            double a = points[tid], b = points[tid + 1];
            double fa = jn_d(i, a);
            for (int it = 0; it < 100; ++it) {
                double m = 0.5 * (a + b);
                double fm = jn_d(i, m);
                if (fa * fm > 0.0) { a = m; fa = fm; } else { b = m; }
            }
            root = 0.5 * (a + b);
        }
        __syncthreads();
        if (tid < cnt) racines[tid] = root;
        __syncthreads();
        if (tid < cnt) points[tid] = racines[tid];
        if (tid < NUM_RAD) zeros_d[i][tid] = racines[tid];
        __syncthreads();
    }

    if (tid < NBASIS) {
        int l = tid / NUM_RAD, k = tid % NUM_RAD;
        double z = zeros_d[l][k];
        g_zeros[l][k] = (float)z;
        g_norms[l][k] = (float)(sqrt(2.0) / fabs(jn_d(l + 1, z)));
    }
}

// --------------------------------------------------------------------------
// Kernel A: rbf[e][l][k] = norms[l][k] * j_l(dist[e]/5 * zeros[l][k])
// One thread per (e, l); writes 6 contiguous floats.
// fp32 recurrence identical to reference _sph_jn.
// --------------------------------------------------------------------------
__global__ void rbf_kernel(const float* __restrict__ dist, int E) {
    int gid = blockIdx.x * blockDim.x + threadIdx.x;
    if (gid >= E * NUM_SPH) return;
    int l = gid % NUM_SPH;
    int e = gid / NUM_SPH;
    float x = dist[e] / 5.0f;

    float outv[NUM_RAD];
    #pragma unroll
    for (int k = 0; k < NUM_RAD; ++k) {
        float z = x * g_zeros[l][k];
        float s, c;
        sincosf(z, &s, &c);                 // precise path (no fast-math)
        float j0 = s / z;
        float res = j0;
        if (l > 0) {
            float j1 = s / (z * z) - c / z;
            float jm = j0, jc = j1;
            for (int i = 1; i < l; ++i) {
                float jn = (2.0f * i + 1.0f) / z * jc - jm;
                jm = jc; jc = jn;
            }
            res = jc;
        }
        outv[k] = g_norms[l][k] * res;
    }

    size_t base = (size_t)gid * NUM_RAD;    // = e*42 + l*6
    // 24B per thread, 8B-aligned -> 3x float2 stores
    float2* p = reinterpret_cast<float2*>(&g_rbf[base]);
    p[0] = make_float2(outv[0], outv[1]);
    p[1] = make_float2(outv[2], outv[3]);
    p[2] = make_float2(outv[4], outv[5]);
}

// --------------------------------------------------------------------------
// Kernel B: out[t, l*6+k] = rbf[idx[t]][l*6+k] * cbf[t][l]
// Phase 1: per-triplet cos + Legendre into SMEM. Phase 2: coalesced gather
// (rbf is L2-resident) + evict-first stores for the 704 MB output stream.
// --------------------------------------------------------------------------
#define TPB 256

__global__ void out_kernel(const float* __restrict__ angle,
                           const int*   __restrict__ idx_kj,
                           float*       __restrict__ out, int T) {
    __shared__ float scbf[TPB][8];   // padded to 8 to dodge bank conflicts
    __shared__ int   sidx[TPB];

    // fp32 of sqrt((2l+1)/(4*pi))
    const float pref[NUM_SPH] = {
        0.28209479177387814f, 0.48860251190291992f, 0.63078313050504009f,
        0.74635266518023080f, 0.84628437532163443f, 0.93560257962738880f,
        1.01710723628205460f
    };

    int t0  = blockIdx.x * TPB;
    int tid = threadIdx.x;
    int t   = t0 + tid;
    int rem = T - t0; if (rem > TPB) rem = TPB;

    if (tid < rem) {
        float ct = cosf(angle[t]);
        sidx[tid] = idx_kj[t];
        float pm = 1.0f, pc = ct;
        scbf[tid][0] = pref[0] * pm;
        scbf[tid][1] = pref[1] * pc;
        #pragma unroll
        for (int l = 2; l < NUM_SPH; ++l) {
            float pn = ((2.0f * l - 1.0f) * ct * pc - (l - 1.0f) * pm) / (float)l;
            pm = pc; pc = pn;
            scbf[tid][l] = pref[l] * pn;
        }
    }
    __syncthreads();

    int tot = rem * NBASIS;
    size_t base = (size_t)t0 * NBASIS;
    for (int i = tid; i < tot; i += TPB) {
        unsigned tl = (unsigned)i / 42u;
        unsigned j  = (unsigned)i - tl * 42u;
        unsigned l  = j / 6u;
        int e = sidx[tl];
        float v = __ldg(&g_rbf[(size_t)e * NBASIS + j]) * scbf[tl][l];
        __stcs(&out[base + (size_t)i], v);   // evict-first: protect L2 for rbf
    }
}

// --------------------------------------------------------------------------
extern "C" void kernel_launch(void* const* d_in, const int* in_sizes, int n_in,
                              void* d_out, int out_size) {
    const float* dist  = (const float*)d_in[0];
    const float* angle = (const float*)d_in[1];
    const int*   idx   = (const int*)  d_in[2];
    float*       out   = (float*)      d_out;
    int E = in_sizes[0];
    int T = in_sizes[1];

    setup_kernel<<<1, 64>>>();

    int nA = E * NUM_SPH;
    rbf_kernel<<<(nA + 255) / 256, 256>>>(dist, E);

    out_kernel<<<(T + TPB - 1) / TPB, TPB>>>(angle, idx, out, T);
}

// round 3
// speedup vs baseline: 1.0178x; 1.0178x over previous
#include <cuda_runtime.h>
#include <math.h>

#define NUM_SPH 7
#define NUM_RAD 6
#define NBASIS  (NUM_SPH * NUM_RAD)   // 42
#define MAX_E   524288
#define TPB     256

// --------------------------------------------------------------------------
// Device-global scratch (static allocation only — no cudaMalloc allowed)
// --------------------------------------------------------------------------
__device__ float g_zeros[NUM_SPH][NUM_RAD];
__device__ float g_norms[NUM_SPH][NUM_RAD];
__device__ float g_rbf[(size_t)MAX_E * NBASIS];   // 88 MB, fits L2

// --------------------------------------------------------------------------
// fp64 spherical Bessel j_n via upward recurrence (matches reference _jn_np)
// --------------------------------------------------------------------------
__device__ double jn_d(int order, double r) {
    double s = sin(r), c = cos(r);
    double j0 = s / r;
    if (order == 0) return j0;
    double j1 = s / (r * r) - c / r;
    double jm = j0, jc = j1;
    for (int i = 1; i < order; ++i) {
        double jnext = (2.0 * i + 1.0) / r * jc - jm;
        jm = jc; jc = jnext;
    }
    return jc;
}

// --------------------------------------------------------------------------
// Setup: replicate _jn_zeros bisection (100 iters) + norms in fp64, cast fp32.
// --------------------------------------------------------------------------
__global__ void setup_kernel() {
    __shared__ double points[16];
    __shared__ double racines[16];
    __shared__ double zeros_d[NUM_SPH][NUM_RAD];
    const double PI = 3.14159265358979323846;
    int tid = threadIdx.x;

    if (tid < NUM_RAD) zeros_d[0][tid] = (tid + 1) * PI;
    if (tid < NUM_RAD + NUM_SPH - 1) points[tid] = (tid + 1) * PI;
    __syncthreads();

    for (int i = 1; i < NUM_SPH; ++i) {
        int cnt = NUM_RAD + NUM_SPH - 1 - i;
        double root = 0.0;
        if (tid < cnt) {
            double a = points[tid], b = points[tid + 1];
            double fa = jn_d(i, a);
            for (int it = 0; it < 100; ++it) {
                double m = 0.5 * (a + b);
                double fm = jn_d(i, m);
                if (fa * fm > 0.0) { a = m; fa = fm; } else { b = m; }
            }
            root = 0.5 * (a + b);
        }
        __syncthreads();
        if (tid < cnt) racines[tid] = root;
        __syncthreads();
        if (tid < cnt) points[tid] = racines[tid];
        if (tid < NUM_RAD) zeros_d[i][tid] = racines[tid];
        __syncthreads();
    }

    if (tid < NBASIS) {
        int l = tid / NUM_RAD, k = tid % NUM_RAD;
        double z = zeros_d[l][k];
        g_zeros[l][k] = (float)z;
        g_norms[l][k] = (float)(sqrt(2.0) / fabs(jn_d(l + 1, z)));
    }
}

// --------------------------------------------------------------------------
// Kernel A: rbf[e][l][k] = norms[l][k] * j_l(dist[e]/5 * zeros[l][k])
// One thread per (e, l); fp32 recurrence identical to reference _sph_jn.
// --------------------------------------------------------------------------
__global__ void rbf_kernel(const float* __restrict__ dist, int E) {
    int gid = blockIdx.x * blockDim.x + threadIdx.x;
    if (gid >= E * NUM_SPH) return;
    int l = gid % NUM_SPH;
    int e = gid / NUM_SPH;
    float x = __ldg(&dist[e]) * 0.2f;

    float outv[NUM_RAD];
    #pragma unroll
    for (int k = 0; k < NUM_RAD; ++k) {
        float z = x * g_zeros[l][k];
        float s, c;
        sincosf(z, &s, &c);                 // precise path (no fast-math)
        float j0 = s / z;
        float res = j0;
        if (l > 0) {
            float j1 = s / (z * z) - c / z;
            float jm = j0, jc = j1;
            for (int i = 1; i < l; ++i) {
                float jn = (2.0f * i + 1.0f) / z * jc - jm;
                jm = jc; jc = jn;
            }
            res = jc;
        }
        outv[k] = g_norms[l][k] * res;
    }

    size_t base = (size_t)gid * NUM_RAD;    // = e*42 + l*6
    float2* p = reinterpret_cast<float2*>(&g_rbf[base]);
    p[0] = make_float2(outv[0], outv[1]);
    p[1] = make_float2(outv[2], outv[3]);
    p[2] = make_float2(outv[4], outv[5]);
}

// --------------------------------------------------------------------------
// Kernel B: out[t, l*6+k] = rbf[idx[t]][l*6+k] * cbf[t][l]
// Fast path (full blocks): incremental (tl, j) indexing, loads batched 7-wide
// for MLP≈7/thread. Stores evict-first to protect L2 for the rbf table.
// --------------------------------------------------------------------------
__global__ void out_kernel(const float* __restrict__ angle,
                           const int*   __restrict__ idx_kj,
                           float*       __restrict__ out, int T) {
    __shared__ float scbf[TPB][8];   // padded to 8 to dodge bank conflicts
    __shared__ int   sidx[TPB];

    // fp32 of sqrt((2l+1)/(4*pi))
    const float pref[NUM_SPH] = {
        0.28209479177387814f, 0.48860251190291992f, 0.63078313050504009f,
        0.74635266518023080f, 0.84628437532163443f, 0.93560257962738880f,
        1.01710723628205460f
    };

    int t0  = blockIdx.x * TPB;
    int tid = threadIdx.x;
    int t   = t0 + tid;
    int rem = T - t0; if (rem > TPB) rem = TPB;

    if (tid < rem) {
        float ct = cosf(angle[t]);
        sidx[tid] = idx_kj[t];
        float pm = 1.0f, pc = ct;
        scbf[tid][0] = pref[0] * pm;
        scbf[tid][1] = pref[1] * pc;
        #pragma unroll
        for (int l = 2; l < NUM_SPH; ++l) {
            float pn = ((2.0f * l - 1.0f) * ct * pc - (l - 1.0f) * pm) / (float)l;
            pm = pc; pc = pn;
            scbf[tid][l] = pref[l] * pn;
        }
    }
    __syncthreads();

    size_t base = (size_t)t0 * NBASIS;

    if (rem == TPB) {
        // ---- fast path: 42 elements/thread, batched 6 x 7 ----
        unsigned tl = (unsigned)tid / 42u;
        unsigned j  = (unsigned)tid - tl * 42u;
        #pragma unroll
        for (int b = 0; b < 6; ++b) {
            float rv[7], cv[7];
            #pragma unroll
            for (int u = 0; u < 7; ++u) {
                unsigned l = (j * 171u) >> 10;        // j/6 for j<42
                int e = sidx[tl];
                rv[u] = __ldg(&g_rbf[(size_t)e * NBASIS + j]);
                cv[u] = scbf[tl][l];
                // advance by TPB=256 elements: 256 = 6*42 + 4
                j += 4u; tl += 6u;
                if (j >= 42u) { j -= 42u; tl += 1u; }
            }
            #pragma unroll
            for (int u = 0; u < 7; ++u) {
                int k = b * 7 + u;
                __stcs(&out[base + (size_t)(tid + k * TPB)], rv[u] * cv[u]);
            }
        }
    } else {
        // ---- tail path (generic) ----
        int tot = rem * NBASIS;
        for (int i = tid; i < tot; i += TPB) {
            unsigned tl = (unsigned)i / 42u;
            unsigned j  = (unsigned)i - tl * 42u;
            unsigned l  = (j * 171u) >> 10;
            int e = sidx[tl];
            float v = __ldg(&g_rbf[(size_t)e * NBASIS + j]) * scbf[tl][l];
            __stcs(&out[base + (size_t)i], v);
        }
    }
}

// --------------------------------------------------------------------------
extern "C" void kernel_launch(void* const* d_in, const int* in_sizes, int n_in,
                              void* d_out, int out_size) {
    const float* dist  = (const float*)d_in[0];
    const float* angle = (const float*)d_in[1];
    const int*   idx   = (const int*)  d_in[2];
    float*       out   = (float*)      d_out;
    int E = in_sizes[0];
    int T = in_sizes[1];

    setup_kernel<<<1, 64>>>();

    int nA = E * NUM_SPH;
    rbf_kernel<<<(nA + 255) / 256, 256>>>(dist, E);

    out_kernel<<<(T + TPB - 1) / TPB, TPB>>>(angle, idx, out, T);
}